// round 9
// baseline (speedup 1.0000x reference)
#include <cuda_runtime.h>
#include <cuda_fp16.h>
#include <cstdint>

// ============================================================================
// S6 forward, reduced:
//   y[t,d] = x[t,d] * softplus(U1[t,d] + b1[d]) * s[t]
//   s[t]   = sum_n (U2[t,n]+b2[n]) * (U3[t,n]+b3[n])
// Pipeline (fp16 tensor-core, fp32 accum; base sm_103 ISA — no tcgen05):
//   1. pack_w1:  W1 -> g_Wh [n][k] fp16 (transposed)
//   2. pack_w23: W2|W3 -> g_W23h [32][k] fp16
//   3. prep:     x -> g_Xh fp16  AND  g_s[t] (fused convert + skinny GEMM)
//   4. gemm:     128x128 CTA, 4 warps @ 64x64, BK=32, 5-stage cp.async,
//                ONE barrier per kt-PAIR, fused epilogue -> y
// ============================================================================

#define NTOK   8192
#define DDIM   1024

#define BM     128
#define BN     128
#define BK     32
#define NKIT   (DDIM / BK)   // 32
#define GTHREADS 128         // 4 warps, 2x2 warp grid, 64x64 per warp

#define PITCH_H   40         // smem row pitch (halves) = 80B: 16B-aligned, ldmatrix conflict-free
#define A_STAGE_H (BM * PITCH_H)               // 5120 halves
#define B_STAGE_H (BN * PITCH_H)               // 5120 halves
#define G_STAGE_H (A_STAGE_H + B_STAGE_H)      // 10240
#define STAGES    5
#define G_SMEM_BYTES (STAGES * G_STAGE_H * 2)  // 102400

__device__ __half g_Wh[(size_t)DDIM * DDIM];   // W1^T, [n][k], 2 MB
__device__ __half g_W23h[32 * DDIM];           // [n][k]: n<16 W2 col, n>=16 W3 col
__device__ __half g_Xh[(size_t)NTOK * DDIM];   // x fp16, 16.8 MB
__device__ float  g_s[NTOK];

// ---------------------------------------------------------------------------
// helpers
// ---------------------------------------------------------------------------
__device__ __forceinline__ uint32_t smem_u32(const void* p) {
    uint32_t a;
    asm("{ .reg .u64 t; cvta.to.shared.u64 t, %1; cvt.u32.u64 %0, t; }" : "=r"(a) : "l"(p));
    return a;
}
__device__ __forceinline__ uint32_t h2_u32(__half2 h) {
    union { __half2 h; uint32_t u; } cvt;
    cvt.h = h;
    return cvt.u;
}
__device__ __forceinline__ void cp_async16(uint32_t dst, const void* src) {
    asm volatile("cp.async.cg.shared.global [%0], [%1], 16;" :: "r"(dst), "l"(src) : "memory");
}
__device__ __forceinline__ void cp_commit() {
    asm volatile("cp.async.commit_group;" ::: "memory");
}
template <int N>
__device__ __forceinline__ void cp_wait() {
    asm volatile("cp.async.wait_group %0;" :: "n"(N) : "memory");
}
__device__ __forceinline__ void ldmx4(uint32_t* r, uint32_t addr) {
    asm volatile("ldmatrix.sync.aligned.m8n8.x4.shared.b16 {%0,%1,%2,%3}, [%4];"
        : "=r"(r[0]), "=r"(r[1]), "=r"(r[2]), "=r"(r[3]) : "r"(addr));
}
__device__ __forceinline__ void mma_f16(float* c, const uint32_t* a, const uint32_t* b) {
    asm volatile(
        "mma.sync.aligned.m16n8k16.row.col.f32.f16.f16.f32 "
        "{%0,%1,%2,%3}, {%4,%5,%6,%7}, {%8,%9}, {%0,%1,%2,%3};"
        : "+f"(c[0]), "+f"(c[1]), "+f"(c[2]), "+f"(c[3])
        : "r"(a[0]), "r"(a[1]), "r"(a[2]), "r"(a[3]), "r"(b[0]), "r"(b[1]));
}
__device__ __forceinline__ float softplus_f(float z) {
    return fmaxf(z, 0.0f) + __logf(1.0f + __expf(-fabsf(z)));
}

// ---------------------------------------------------------------------------
// Kernel 1a: Wh[n][k] = fp16(W1[k][n])
// ---------------------------------------------------------------------------
__global__ void __launch_bounds__(1024) s6_pack_w1(const float* __restrict__ W1) {
    __shared__ float tile[32][33];
    const int tx = threadIdx.x, ty = threadIdx.y;
    const int k = blockIdx.y * 32 + ty;
    const int n = blockIdx.x * 32 + tx;
    tile[ty][tx] = W1[(size_t)k * DDIM + n];
    __syncthreads();
    const int nn = blockIdx.x * 32 + ty;
    const int kk = blockIdx.y * 32 + tx;
    g_Wh[(size_t)nn * DDIM + kk] = __float2half_rn(tile[tx][ty]);
}

// ---------------------------------------------------------------------------
// Kernel 1b: W23h[n][k]
// ---------------------------------------------------------------------------
__global__ void __launch_bounds__(256) s6_pack_w23(const float* __restrict__ W2,
                                                   const float* __restrict__ W3) {
    const int idx = blockIdx.x * 256 + threadIdx.x;   // 32768
    const int n = idx >> 10;
    const int k = idx & 1023;
    const float v = (n < 16) ? W2[(size_t)k * 16 + n] : W3[(size_t)k * 16 + (n - 16)];
    g_W23h[n * DDIM + k] = __float2half_rn(v);
}

// ---------------------------------------------------------------------------
// Kernel 2: prep — fused x->fp16 convert + s[t] computation
// ---------------------------------------------------------------------------
#define P_PITCH 136
#define P_STG   (32 * P_PITCH)

__global__ void __launch_bounds__(256) s6_prep(const float* __restrict__ x,
                                               const float* __restrict__ b2,
                                               const float* __restrict__ b3) {
    __shared__ __half sX[2][P_STG];
    __shared__ __half sW[2][P_STG];
    __shared__ float sU[32][33];

    const int tid = threadIdx.x;
    const int wid = tid >> 5;
    const int lane = tid & 31;
    const int grp = lane >> 2;
    const int qid = lane & 3;
    const int tok0 = blockIdx.x * 32;
    const uint32_t sW_u[2] = { smem_u32(sW[0]), smem_u32(sW[1]) };

    for (int i = tid; i < 32 * 33; i += 256) ((float*)sU)[i] = 0.0f;

#pragma unroll
    for (int j = 0; j < 2; ++j) {
        const int i = tid + j * 256;
        const int row = i >> 4, ch = i & 15;
        cp_async16(sW_u[0] + (uint32_t)(row * P_PITCH + ch * 8) * 2,
                   g_W23h + row * DDIM + ch * 8);
    }
    cp_commit();

    const int t = tid >> 3;
    const int co = (tid & 7) * 16;

    float acc[2][4][4];
#pragma unroll
    for (int f = 0; f < 2; ++f)
#pragma unroll
        for (int g = 0; g < 4; ++g)
#pragma unroll
            for (int q = 0; q < 4; ++q) acc[f][g][q] = 0.0f;

    for (int c = 0; c < 8; ++c) {
        const int st = c & 1;
        const float* src = x + (size_t)(tok0 + t) * DDIM + c * 128 + co;
        float4 v0 = *(const float4*)(src + 0);
        float4 v1 = *(const float4*)(src + 4);
        float4 v2 = *(const float4*)(src + 8);
        float4 v3 = *(const float4*)(src + 12);
        uint4 pk0, pk1;
        pk0.x = h2_u32(__float22half2_rn(make_float2(v0.x, v0.y)));
        pk0.y = h2_u32(__float22half2_rn(make_float2(v0.z, v0.w)));
        pk0.z = h2_u32(__float22half2_rn(make_float2(v1.x, v1.y)));
        pk0.w = h2_u32(__float22half2_rn(make_float2(v1.z, v1.w)));
        pk1.x = h2_u32(__float22half2_rn(make_float2(v2.x, v2.y)));
        pk1.y = h2_u32(__float22half2_rn(make_float2(v2.z, v2.w)));
        pk1.z = h2_u32(__float22half2_rn(make_float2(v3.x, v3.y)));
        pk1.w = h2_u32(__float22half2_rn(make_float2(v3.z, v3.w)));
        *(uint4*)(&sX[st][t * P_PITCH + co])     = pk0;
        *(uint4*)(&sX[st][t * P_PITCH + co + 8]) = pk1;
        __half* gx = g_Xh + (size_t)(tok0 + t) * DDIM + c * 128 + co;
        *(uint4*)(gx)     = pk0;
        *(uint4*)(gx + 8) = pk1;

        cp_wait<0>();
        __syncthreads();

        if (c < 7) {
            const int ns = (c + 1) & 1;
#pragma unroll
            for (int j = 0; j < 2; ++j) {
                const int i = tid + j * 256;
                const int row = i >> 4, ch = i & 15;
                cp_async16(sW_u[ns] + (uint32_t)(row * P_PITCH + ch * 8) * 2,
                           g_W23h + row * DDIM + (c + 1) * 128 + ch * 8);
            }
            cp_commit();
        }

        const int koff = wid * 16 + 2 * qid;
#pragma unroll
        for (int f = 0; f < 2; ++f) {
            const __half* p = &sX[st][(f * 16 + grp) * P_PITCH + koff];
            uint32_t a[4];
            a[0] = *(const uint32_t*)p;
            a[1] = *(const uint32_t*)(p + 8 * P_PITCH);
            a[2] = *(const uint32_t*)(p + 8);
            a[3] = *(const uint32_t*)(p + 8 * P_PITCH + 8);
#pragma unroll
            for (int g = 0; g < 4; ++g) {
                const __half* q = &sW[st][(g * 8 + grp) * P_PITCH + koff];
                uint32_t b[2];
                b[0] = *(const uint32_t*)q;
                b[1] = *(const uint32_t*)(q + 8);
                mma_f16(acc[f][g], a, b);
            }
        }
        __syncthreads();
    }

#pragma unroll
    for (int f = 0; f < 2; ++f)
#pragma unroll
        for (int g = 0; g < 4; ++g) {
            atomicAdd(&sU[f * 16 + grp][g * 8 + 2 * qid],         acc[f][g][0]);
            atomicAdd(&sU[f * 16 + grp][g * 8 + 2 * qid + 1],     acc[f][g][1]);
            atomicAdd(&sU[f * 16 + grp + 8][g * 8 + 2 * qid],     acc[f][g][2]);
            atomicAdd(&sU[f * 16 + grp + 8][g * 8 + 2 * qid + 1], acc[f][g][3]);
        }
    __syncthreads();

    if (tid < 32) {
        float s = 0.0f;
#pragma unroll
        for (int n = 0; n < 16; ++n)
            s += (sU[tid][n] + __ldg(b2 + n)) * (sU[tid][n + 16] + __ldg(b3 + n));
        g_s[tok0 + tid] = s;
    }
}

// ---------------------------------------------------------------------------
// Kernel 3: main GEMM — 128x128, 4 warps @ 64x64, 5 stages, barrier per pair
// ---------------------------------------------------------------------------
__device__ __forceinline__ void g_prefetch(uint32_t smem_base_u, int stage, int kt,
                                           int m0, int n0, int tid) {
    const uint32_t st = smem_base_u + (uint32_t)(stage * G_STAGE_H) * 2;
#pragma unroll
    for (int i = 0; i < 4; ++i) {           // A: 128 rows x 4 x 16B
        const int c = tid + i * GTHREADS;
        const int row = c >> 2, ch = c & 3;
        cp_async16(st + (uint32_t)(row * PITCH_H + ch * 8) * 2,
                   g_Xh + (size_t)(m0 + row) * DDIM + kt * BK + ch * 8);
    }
#pragma unroll
    for (int i = 0; i < 4; ++i) {           // B: 128 rows x 4 x 16B
        const int c = tid + i * GTHREADS;
        const int row = c >> 2, ch = c & 3;
        cp_async16(st + (uint32_t)(A_STAGE_H + row * PITCH_H + ch * 8) * 2,
                   g_Wh + (size_t)(n0 + row) * DDIM + kt * BK + ch * 8);
    }
}

__global__ void __launch_bounds__(GTHREADS, 2) s6_gemm(const float* __restrict__ x,
                                                       const float* __restrict__ b1,
                                                       float* __restrict__ y) {
    extern __shared__ __half smh[];
    const uint32_t sm_u = smem_u32(smh);

    const int tid = threadIdx.x;
    const int wid = tid >> 5;
    const int lane = tid & 31;
    const int grp = lane >> 2;
    const int qid = lane & 3;
    const int wm = wid & 1;      // 2 warps along M (64 each)
    const int wn = wid >> 1;     // 2 warps along N (64 each)
    const int m0 = blockIdx.y * BM;
    const int n0 = blockIdx.x * BN;

    // ldmatrix per-lane base offsets (half units within a stage)
    const uint32_t aIdx = (uint32_t)((wm * 64 + (lane & 15)) * PITCH_H + (lane >> 4) * 8);
    const uint32_t bIdx = (uint32_t)(A_STAGE_H +
        (wn * 64 + ((lane >> 4) & 1) * 8 + (lane & 7)) * PITCH_H + ((lane >> 3) & 1) * 8);

    float acc[4][8][4];
#pragma unroll
    for (int f = 0; f < 4; ++f)
#pragma unroll
        for (int g = 0; g < 8; ++g)
#pragma unroll
            for (int q = 0; q < 4; ++q) acc[f][g][q] = 0.0f;

    g_prefetch(sm_u, 0, 0, m0, n0, tid);
    cp_commit();
    g_prefetch(sm_u, 1, 1, m0, n0, tid);
    cp_commit();
    g_prefetch(sm_u, 2, 2, m0, n0, tid);
    cp_commit();

    for (int p = 0; p < NKIT / 2; ++p) {
        // stages 2p, 2p+1 ready (all groups but the newest have landed)
        cp_wait<1>();
        __syncthreads();

        const int pf0 = 2 * p + 3;
        if (pf0 < NKIT) g_prefetch(sm_u, pf0 % STAGES, pf0, m0, n0, tid);
        cp_commit();
        const int pf1 = 2 * p + 4;
        if (pf1 < NKIT) g_prefetch(sm_u, pf1 % STAGES, pf1, m0, n0, tid);
        cp_commit();

#pragma unroll
        for (int h = 0; h < 2; ++h) {
            const int kt = 2 * p + h;
            const uint32_t stg = sm_u + (uint32_t)((kt % STAGES) * G_STAGE_H) * 2;
#pragma unroll
            for (int ks = 0; ks < 2; ++ks) {
                uint32_t af[4][4], bf[8][2];
#pragma unroll
                for (int f = 0; f < 4; ++f)
                    ldmx4(af[f], stg + (aIdx + (uint32_t)(f * 16 * PITCH_H + ks * 16)) * 2);
#pragma unroll
                for (int t = 0; t < 4; ++t) {
                    uint32_t bq[4];
                    ldmx4(bq, stg + (bIdx + (uint32_t)(t * 16 * PITCH_H + ks * 16)) * 2);
                    bf[2 * t][0]     = bq[0];
                    bf[2 * t][1]     = bq[1];
                    bf[2 * t + 1][0] = bq[2];
                    bf[2 * t + 1][1] = bq[3];
                }
#pragma unroll
                for (int f = 0; f < 4; ++f)
#pragma unroll
                    for (int g = 0; g < 8; ++g)
                        mma_f16(acc[f][g], af[f], bf[g]);
            }
        }
    }

    // fused epilogue: y = x * softplus(acc + b1) * s
#pragma unroll
    for (int f = 0; f < 4; ++f) {
        const int r0 = m0 + wm * 64 + f * 16 + grp;
        const int r1 = r0 + 8;
        const float s0 = __ldg(g_s + r0);
        const float s1 = __ldg(g_s + r1);
        const float* xr0 = x + (size_t)r0 * DDIM;
        const float* xr1 = x + (size_t)r1 * DDIM;
        float* yr0 = y + (size_t)r0 * DDIM;
        float* yr1 = y + (size_t)r1 * DDIM;
#pragma unroll
        for (int g = 0; g < 8; ++g) {
            const int c = n0 + wn * 64 + g * 8 + 2 * qid;
            const float2 bv = *(const float2*)(b1 + c);
            const float2 x0 = *(const float2*)(xr0 + c);
            const float2 x1 = *(const float2*)(xr1 + c);
            float2 o0, o1;
            o0.x = x0.x * softplus_f(acc[f][g][0] + bv.x) * s0;
            o0.y = x0.y * softplus_f(acc[f][g][1] + bv.y) * s0;
            o1.x = x1.x * softplus_f(acc[f][g][2] + bv.x) * s1;
            o1.y = x1.y * softplus_f(acc[f][g][3] + bv.y) * s1;
            *(float2*)(yr0 + c) = o0;
            *(float2*)(yr1 + c) = o1;
        }
    }
}

// ---------------------------------------------------------------------------
// Launch
// ---------------------------------------------------------------------------
extern "C" void kernel_launch(void* const* d_in, const int* in_sizes, int n_in,
                              void* d_out, int out_size) {
    const float* x  = (const float*)d_in[0];
    const float* W1 = (const float*)d_in[1];
    const float* b1 = (const float*)d_in[2];
    const float* W2 = (const float*)d_in[3];
    const float* b2 = (const float*)d_in[4];
    const float* W3 = (const float*)d_in[5];
    const float* b3 = (const float*)d_in[6];
    float* y = (float*)d_out;

    s6_pack_w23<<<128, 256>>>(W2, W3);
    s6_pack_w1<<<dim3(32, 32), dim3(32, 32)>>>(W1);
    s6_prep<<<NTOK / 32, 256>>>(x, b2, b3);

    cudaFuncSetAttribute(s6_gemm, cudaFuncAttributeMaxDynamicSharedMemorySize, G_SMEM_BYTES);
    s6_gemm<<<dim3(DDIM / BN, NTOK / BM), GTHREADS, G_SMEM_BYTES>>>(x, b1, y);
}

// round 10
// speedup vs baseline: 1.1095x; 1.1095x over previous
#include <cuda_runtime.h>
#include <cuda_fp16.h>
#include <cstdint>

// ============================================================================
// S6 forward, reduced:
//   y[t,d] = x[t,d] * softplus(U1[t,d] + b1[d]) * s[t]
//   s[t]   = sum_n (U2[t,n]+b2[n]) * (U3[t,n]+b3[n])
// Pipeline (fp16 tensor-core, fp32 accum; base sm_103 ISA — no tcgen05):
//   1. pack_w1:  W1 -> g_Wh [n][k] fp16 (transposed)
//   2. pack_w23: W2|W3 -> g_W23h [32][k] fp16
//   3. prep:     x -> g_Xh fp16  AND  g_s[t] (fused convert + skinny GEMM)
//   4. gemm:     64x128 CTA, 4 warps @ 32x64 (low regs -> 4 CTAs/SM),
//                BK=32, 3-stage cp.async, fused epilogue -> y
// ============================================================================

#define NTOK   8192
#define DDIM   1024

#define BM     64
#define BN     128
#define BK     32
#define NKIT   (DDIM / BK)   // 32
#define GTHREADS 128         // 4 warps, 2x2 warp grid, 32x64 per warp

#define PITCH_H   40         // smem row pitch (halves) = 80B: 16B-aligned, ldmatrix conflict-free
#define A_STAGE_H (BM * PITCH_H)               // 2560 halves
#define B_STAGE_H (BN * PITCH_H)               // 5120 halves
#define G_STAGE_H (A_STAGE_H + B_STAGE_H)      // 7680
#define STAGES    3
#define G_SMEM_BYTES (STAGES * G_STAGE_H * 2)  // 46080

__device__ __half g_Wh[(size_t)DDIM * DDIM];   // W1^T, [n][k], 2 MB
__device__ __half g_W23h[32 * DDIM];           // [n][k]: n<16 W2 col, n>=16 W3 col
__device__ __half g_Xh[(size_t)NTOK * DDIM];   // x fp16, 16.8 MB
__device__ float  g_s[NTOK];

// ---------------------------------------------------------------------------
// helpers
// ---------------------------------------------------------------------------
__device__ __forceinline__ uint32_t smem_u32(const void* p) {
    uint32_t a;
    asm("{ .reg .u64 t; cvta.to.shared.u64 t, %1; cvt.u32.u64 %0, t; }" : "=r"(a) : "l"(p));
    return a;
}
__device__ __forceinline__ uint32_t h2_u32(__half2 h) {
    union { __half2 h; uint32_t u; } cvt;
    cvt.h = h;
    return cvt.u;
}
__device__ __forceinline__ void cp_async16(uint32_t dst, const void* src) {
    asm volatile("cp.async.cg.shared.global [%0], [%1], 16;" :: "r"(dst), "l"(src) : "memory");
}
__device__ __forceinline__ void cp_commit() {
    asm volatile("cp.async.commit_group;" ::: "memory");
}
template <int N>
__device__ __forceinline__ void cp_wait() {
    asm volatile("cp.async.wait_group %0;" :: "n"(N) : "memory");
}
__device__ __forceinline__ void ldmx4(uint32_t* r, uint32_t addr) {
    asm volatile("ldmatrix.sync.aligned.m8n8.x4.shared.b16 {%0,%1,%2,%3}, [%4];"
        : "=r"(r[0]), "=r"(r[1]), "=r"(r[2]), "=r"(r[3]) : "r"(addr));
}
__device__ __forceinline__ void mma_f16(float* c, const uint32_t* a, const uint32_t* b) {
    asm volatile(
        "mma.sync.aligned.m16n8k16.row.col.f32.f16.f16.f32 "
        "{%0,%1,%2,%3}, {%4,%5,%6,%7}, {%8,%9}, {%0,%1,%2,%3};"
        : "+f"(c[0]), "+f"(c[1]), "+f"(c[2]), "+f"(c[3])
        : "r"(a[0]), "r"(a[1]), "r"(a[2]), "r"(a[3]), "r"(b[0]), "r"(b[1]));
}
__device__ __forceinline__ float softplus_f(float z) {
    return fmaxf(z, 0.0f) + __logf(1.0f + __expf(-fabsf(z)));
}

// ---------------------------------------------------------------------------
// Kernel 1a: Wh[n][k] = fp16(W1[k][n])
// ---------------------------------------------------------------------------
__global__ void __launch_bounds__(1024) s6_pack_w1(const float* __restrict__ W1) {
    __shared__ float tile[32][33];
    const int tx = threadIdx.x, ty = threadIdx.y;
    const int k = blockIdx.y * 32 + ty;
    const int n = blockIdx.x * 32 + tx;
    tile[ty][tx] = W1[(size_t)k * DDIM + n];
    __syncthreads();
    const int nn = blockIdx.x * 32 + ty;
    const int kk = blockIdx.y * 32 + tx;
    g_Wh[(size_t)nn * DDIM + kk] = __float2half_rn(tile[tx][ty]);
}

// ---------------------------------------------------------------------------
// Kernel 1b: W23h[n][k]
// ---------------------------------------------------------------------------
__global__ void __launch_bounds__(256) s6_pack_w23(const float* __restrict__ W2,
                                                   const float* __restrict__ W3) {
    const int idx = blockIdx.x * 256 + threadIdx.x;   // 32768
    const int n = idx >> 10;
    const int k = idx & 1023;
    const float v = (n < 16) ? W2[(size_t)k * 16 + n] : W3[(size_t)k * 16 + (n - 16)];
    g_W23h[n * DDIM + k] = __float2half_rn(v);
}

// ---------------------------------------------------------------------------
// Kernel 2: prep — fused x->fp16 convert + s[t] computation
// ---------------------------------------------------------------------------
#define P_PITCH 136
#define P_STG   (32 * P_PITCH)

__global__ void __launch_bounds__(256) s6_prep(const float* __restrict__ x,
                                               const float* __restrict__ b2,
                                               const float* __restrict__ b3) {
    __shared__ __half sX[2][P_STG];
    __shared__ __half sW[2][P_STG];
    __shared__ float sU[32][33];

    const int tid = threadIdx.x;
    const int wid = tid >> 5;
    const int lane = tid & 31;
    const int grp = lane >> 2;
    const int qid = lane & 3;
    const int tok0 = blockIdx.x * 32;
    const uint32_t sW_u[2] = { smem_u32(sW[0]), smem_u32(sW[1]) };

    for (int i = tid; i < 32 * 33; i += 256) ((float*)sU)[i] = 0.0f;

#pragma unroll
    for (int j = 0; j < 2; ++j) {
        const int i = tid + j * 256;
        const int row = i >> 4, ch = i & 15;
        cp_async16(sW_u[0] + (uint32_t)(row * P_PITCH + ch * 8) * 2,
                   g_W23h + row * DDIM + ch * 8);
    }
    cp_commit();

    const int t = tid >> 3;
    const int co = (tid & 7) * 16;

    float acc[2][4][4];
#pragma unroll
    for (int f = 0; f < 2; ++f)
#pragma unroll
        for (int g = 0; g < 4; ++g)
#pragma unroll
            for (int q = 0; q < 4; ++q) acc[f][g][q] = 0.0f;

    for (int c = 0; c < 8; ++c) {
        const int st = c & 1;
        const float* src = x + (size_t)(tok0 + t) * DDIM + c * 128 + co;
        float4 v0 = *(const float4*)(src + 0);
        float4 v1 = *(const float4*)(src + 4);
        float4 v2 = *(const float4*)(src + 8);
        float4 v3 = *(const float4*)(src + 12);
        uint4 pk0, pk1;
        pk0.x = h2_u32(__float22half2_rn(make_float2(v0.x, v0.y)));
        pk0.y = h2_u32(__float22half2_rn(make_float2(v0.z, v0.w)));
        pk0.z = h2_u32(__float22half2_rn(make_float2(v1.x, v1.y)));
        pk0.w = h2_u32(__float22half2_rn(make_float2(v1.z, v1.w)));
        pk1.x = h2_u32(__float22half2_rn(make_float2(v2.x, v2.y)));
        pk1.y = h2_u32(__float22half2_rn(make_float2(v2.z, v2.w)));
        pk1.z = h2_u32(__float22half2_rn(make_float2(v3.x, v3.y)));
        pk1.w = h2_u32(__float22half2_rn(make_float2(v3.z, v3.w)));
        *(uint4*)(&sX[st][t * P_PITCH + co])     = pk0;
        *(uint4*)(&sX[st][t * P_PITCH + co + 8]) = pk1;
        __half* gx = g_Xh + (size_t)(tok0 + t) * DDIM + c * 128 + co;
        *(uint4*)(gx)     = pk0;
        *(uint4*)(gx + 8) = pk1;

        cp_wait<0>();
        __syncthreads();

        if (c < 7) {
            const int ns = (c + 1) & 1;
#pragma unroll
            for (int j = 0; j < 2; ++j) {
                const int i = tid + j * 256;
                const int row = i >> 4, ch = i & 15;
                cp_async16(sW_u[ns] + (uint32_t)(row * P_PITCH + ch * 8) * 2,
                           g_W23h + row * DDIM + (c + 1) * 128 + ch * 8);
            }
            cp_commit();
        }

        const int koff = wid * 16 + 2 * qid;
#pragma unroll
        for (int f = 0; f < 2; ++f) {
            const __half* p = &sX[st][(f * 16 + grp) * P_PITCH + koff];
            uint32_t a[4];
            a[0] = *(const uint32_t*)p;
            a[1] = *(const uint32_t*)(p + 8 * P_PITCH);
            a[2] = *(const uint32_t*)(p + 8);
            a[3] = *(const uint32_t*)(p + 8 * P_PITCH + 8);
#pragma unroll
            for (int g = 0; g < 4; ++g) {
                const __half* q = &sW[st][(g * 8 + grp) * P_PITCH + koff];
                uint32_t b[2];
                b[0] = *(const uint32_t*)q;
                b[1] = *(const uint32_t*)(q + 8);
                mma_f16(acc[f][g], a, b);
            }
        }
        __syncthreads();
    }

#pragma unroll
    for (int f = 0; f < 2; ++f)
#pragma unroll
        for (int g = 0; g < 4; ++g) {
            atomicAdd(&sU[f * 16 + grp][g * 8 + 2 * qid],         acc[f][g][0]);
            atomicAdd(&sU[f * 16 + grp][g * 8 + 2 * qid + 1],     acc[f][g][1]);
            atomicAdd(&sU[f * 16 + grp + 8][g * 8 + 2 * qid],     acc[f][g][2]);
            atomicAdd(&sU[f * 16 + grp + 8][g * 8 + 2 * qid + 1], acc[f][g][3]);
        }
    __syncthreads();

    if (tid < 32) {
        float s = 0.0f;
#pragma unroll
        for (int n = 0; n < 16; ++n)
            s += (sU[tid][n] + __ldg(b2 + n)) * (sU[tid][n + 16] + __ldg(b3 + n));
        g_s[tok0 + tid] = s;
    }
}

// ---------------------------------------------------------------------------
// Kernel 3: main GEMM — 64x128 CTA, 4 warps @ 32x64, 3 stages, low regs
// ---------------------------------------------------------------------------
__device__ __forceinline__ void g_prefetch(uint32_t smem_base_u, int stage, int kt,
                                           int m0, int n0, int tid) {
    const uint32_t st = smem_base_u + (uint32_t)(stage * G_STAGE_H) * 2;
#pragma unroll
    for (int i = 0; i < 2; ++i) {           // A: 64 rows x 4 x 16B
        const int c = tid + i * GTHREADS;
        const int row = c >> 2, ch = c & 3;
        cp_async16(st + (uint32_t)(row * PITCH_H + ch * 8) * 2,
                   g_Xh + (size_t)(m0 + row) * DDIM + kt * BK + ch * 8);
    }
#pragma unroll
    for (int i = 0; i < 4; ++i) {           // B: 128 rows x 4 x 16B
        const int c = tid + i * GTHREADS;
        const int row = c >> 2, ch = c & 3;
        cp_async16(st + (uint32_t)(A_STAGE_H + row * PITCH_H + ch * 8) * 2,
                   g_Wh + (size_t)(n0 + row) * DDIM + kt * BK + ch * 8);
    }
}

__global__ void __launch_bounds__(GTHREADS, 4) s6_gemm(const float* __restrict__ x,
                                                       const float* __restrict__ b1,
                                                       float* __restrict__ y) {
    extern __shared__ __half smh[];
    const uint32_t sm_u = smem_u32(smh);

    const int tid = threadIdx.x;
    const int wid = tid >> 5;
    const int lane = tid & 31;
    const int grp = lane >> 2;
    const int qid = lane & 3;
    const int wm = wid & 1;      // 2 warps along M (32 each)
    const int wn = wid >> 1;     // 2 warps along N (64 each)
    const int m0 = blockIdx.y * BM;
    const int n0 = blockIdx.x * BN;

    // ldmatrix per-lane base offsets (half units within a stage)
    const uint32_t aIdx = (uint32_t)((wm * 32 + (lane & 15)) * PITCH_H + (lane >> 4) * 8);
    const uint32_t bIdx = (uint32_t)(A_STAGE_H +
        (wn * 64 + ((lane >> 4) & 1) * 8 + (lane & 7)) * PITCH_H + ((lane >> 3) & 1) * 8);

    float acc[2][8][4];
#pragma unroll
    for (int f = 0; f < 2; ++f)
#pragma unroll
        for (int g = 0; g < 8; ++g)
#pragma unroll
            for (int q = 0; q < 4; ++q) acc[f][g][q] = 0.0f;

    g_prefetch(sm_u, 0, 0, m0, n0, tid);
    cp_commit();
    g_prefetch(sm_u, 1, 1, m0, n0, tid);
    cp_commit();

    for (int kt = 0; kt < NKIT; ++kt) {
        const int s = kt % STAGES;
        cp_wait<1>();
        __syncthreads();

        const int pf = kt + 2;
        if (pf < NKIT) g_prefetch(sm_u, pf % STAGES, pf, m0, n0, tid);
        cp_commit();

        const uint32_t stg = sm_u + (uint32_t)(s * G_STAGE_H) * 2;
#pragma unroll
        for (int ks = 0; ks < 2; ++ks) {
            uint32_t af[2][4], bf[8][2];
#pragma unroll
            for (int f = 0; f < 2; ++f)
                ldmx4(af[f], stg + (aIdx + (uint32_t)(f * 16 * PITCH_H + ks * 16)) * 2);
#pragma unroll
            for (int h = 0; h < 4; ++h) {
                uint32_t bq[4];
                ldmx4(bq, stg + (bIdx + (uint32_t)(h * 16 * PITCH_H + ks * 16)) * 2);
                bf[2 * h][0]     = bq[0];
                bf[2 * h][1]     = bq[1];
                bf[2 * h + 1][0] = bq[2];
                bf[2 * h + 1][1] = bq[3];
            }
#pragma unroll
            for (int f = 0; f < 2; ++f)
#pragma unroll
                for (int g = 0; g < 8; ++g)
                    mma_f16(acc[f][g], af[f], bf[g]);
        }
    }

    // fused epilogue: y = x * softplus(acc + b1) * s
#pragma unroll
    for (int f = 0; f < 2; ++f) {
        const int r0 = m0 + wm * 32 + f * 16 + grp;
        const int r1 = r0 + 8;
        const float s0 = __ldg(g_s + r0);
        const float s1 = __ldg(g_s + r1);
        const float* xr0 = x + (size_t)r0 * DDIM;
        const float* xr1 = x + (size_t)r1 * DDIM;
        float* yr0 = y + (size_t)r0 * DDIM;
        float* yr1 = y + (size_t)r1 * DDIM;
#pragma unroll
        for (int g = 0; g < 8; ++g) {
            const int c = n0 + wn * 64 + g * 8 + 2 * qid;
            const float2 bv = *(const float2*)(b1 + c);
            const float2 x0 = *(const float2*)(xr0 + c);
            const float2 x1 = *(const float2*)(xr1 + c);
            float2 o0, o1;
            o0.x = x0.x * softplus_f(acc[f][g][0] + bv.x) * s0;
            o0.y = x0.y * softplus_f(acc[f][g][1] + bv.y) * s0;
            o1.x = x1.x * softplus_f(acc[f][g][2] + bv.x) * s1;
            o1.y = x1.y * softplus_f(acc[f][g][3] + bv.y) * s1;
            *(float2*)(yr0 + c) = o0;
            *(float2*)(yr1 + c) = o1;
        }
    }
}

// ---------------------------------------------------------------------------
// Launch
// ---------------------------------------------------------------------------
extern "C" void kernel_launch(void* const* d_in, const int* in_sizes, int n_in,
                              void* d_out, int out_size) {
    const float* x  = (const float*)d_in[0];
    const float* W1 = (const float*)d_in[1];
    const float* b1 = (const float*)d_in[2];
    const float* W2 = (const float*)d_in[3];
    const float* b2 = (const float*)d_in[4];
    const float* W3 = (const float*)d_in[5];
    const float* b3 = (const float*)d_in[6];
    float* y = (float*)d_out;

    s6_pack_w23<<<128, 256>>>(W2, W3);
    s6_pack_w1<<<dim3(32, 32), dim3(32, 32)>>>(W1);
    s6_prep<<<NTOK / 32, 256>>>(x, b2, b3);

    cudaFuncSetAttribute(s6_gemm, cudaFuncAttributeMaxDynamicSharedMemorySize, G_SMEM_BYTES);
    s6_gemm<<<dim3(DDIM / BN, NTOK / BM), GTHREADS, G_SMEM_BYTES>>>(x, b1, y);
}

// round 12
// speedup vs baseline: 1.1807x; 1.0642x over previous
#include <cuda_runtime.h>
#include <cuda_fp16.h>
#include <cstdint>

// ============================================================================
// S6 forward, reduced:
//   y[t,d] = x[t,d] * softplus(U1[t,d] + b1[d]) * s[t]
//   s[t]   = sum_n (U2[t,n]+b2[n]) * (U3[t,n]+b3[n])
// Pipeline (fp16 mma.sync, fp32 accum; base sm_103 ISA — no tcgen05):
//   1. pack:  W1 -> g_Wh [n][k] fp16 (transposed); W2|W3 -> g_W23h (merged)
//   2. prep:  x -> g_Xh fp16 AND g_s[t]  (512 CTAs x 16 tokens)
//   3. gemm:  128x128 CTA, 4 warps @ 64x64, ldmatrix, 3-stage (R7 config —
//             measured at the legacy-HMMA instruction-rate ceiling)
// ============================================================================

#define NTOK   8192
#define DDIM   1024

#define BM     128
#define BN     128
#define BK     32
#define NKIT   (DDIM / BK)   // 32
#define GTHREADS 128         // 4 warps, 2x2 warp grid, 64x64 per warp

#define PITCH_H   40         // smem row pitch (halves) = 80B
#define A_STAGE_H (BM * PITCH_H)               // 5120 halves
#define B_STAGE_H (BN * PITCH_H)               // 5120 halves
#define G_STAGE_H (A_STAGE_H + B_STAGE_H)      // 10240
#define STAGES    3
#define G_SMEM_BYTES (STAGES * G_STAGE_H * 2)  // 61440

__device__ __half g_Wh[(size_t)DDIM * DDIM];   // W1^T, [n][k], 2 MB
__device__ __half g_W23h[32 * DDIM];           // [n][k]: n<16 W2 col, n>=16 W3 col
__device__ __half g_Xh[(size_t)NTOK * DDIM];   // x fp16, 16.8 MB
__device__ float  g_s[NTOK];

// ---------------------------------------------------------------------------
// helpers
// ---------------------------------------------------------------------------
__device__ __forceinline__ uint32_t smem_u32(const void* p) {
    uint32_t a;
    asm("{ .reg .u64 t; cvta.to.shared.u64 t, %1; cvt.u32.u64 %0, t; }" : "=r"(a) : "l"(p));
    return a;
}
__device__ __forceinline__ uint32_t h2_u32(__half2 h) {
    union { __half2 h; uint32_t u; } cvt;
    cvt.h = h;
    return cvt.u;
}
__device__ __forceinline__ void cp_async16(uint32_t dst, const void* src) {
    asm volatile("cp.async.cg.shared.global [%0], [%1], 16;" :: "r"(dst), "l"(src) : "memory");
}
__device__ __forceinline__ void cp_commit() {
    asm volatile("cp.async.commit_group;" ::: "memory");
}
template <int N>
__device__ __forceinline__ void cp_wait() {
    asm volatile("cp.async.wait_group %0;" :: "n"(N) : "memory");
}
__device__ __forceinline__ void ldmx4(uint32_t* r, uint32_t addr) {
    asm volatile("ldmatrix.sync.aligned.m8n8.x4.shared.b16 {%0,%1,%2,%3}, [%4];"
        : "=r"(r[0]), "=r"(r[1]), "=r"(r[2]), "=r"(r[3]) : "r"(addr));
}
__device__ __forceinline__ void mma_f16(float* c, const uint32_t* a, const uint32_t* b) {
    asm volatile(
        "mma.sync.aligned.m16n8k16.row.col.f32.f16.f16.f32 "
        "{%0,%1,%2,%3}, {%4,%5,%6,%7}, {%8,%9}, {%0,%1,%2,%3};"
        : "+f"(c[0]), "+f"(c[1]), "+f"(c[2]), "+f"(c[3])
        : "r"(a[0]), "r"(a[1]), "r"(a[2]), "r"(a[3]), "r"(b[0]), "r"(b[1]));
}
__device__ __forceinline__ float softplus_f(float z) {
    return fmaxf(z, 0.0f) + __logf(1.0f + __expf(-fabsf(z)));
}

// ---------------------------------------------------------------------------
// Kernel 1: merged pack — blocks [0,1024): W1 transpose; [1024,1056): W23
// ---------------------------------------------------------------------------
__global__ void __launch_bounds__(1024) s6_pack(const float* __restrict__ W1,
                                                const float* __restrict__ W2,
                                                const float* __restrict__ W3) {
    const int bid = blockIdx.x;
    const int tx = threadIdx.x, ty = threadIdx.y;
    if (bid < 1024) {
        __shared__ float tile[32][33];
        const int bx = bid & 31, by = bid >> 5;
        const int k = by * 32 + ty;
        const int n = bx * 32 + tx;
        tile[ty][tx] = W1[(size_t)k * DDIM + n];
        __syncthreads();
        const int nn = bx * 32 + ty;
        const int kk = by * 32 + tx;
        g_Wh[(size_t)nn * DDIM + kk] = __float2half_rn(tile[tx][ty]);
    } else {
        const int idx = (bid - 1024) * 1024 + ty * 32 + tx;   // 32768 total
        const int n = idx >> 10;
        const int k = idx & 1023;
        const float v = (n < 16) ? W2[(size_t)k * 16 + n] : W3[(size_t)k * 16 + (n - 16)];
        g_W23h[n * DDIM + k] = __float2half_rn(v);
    }
}

// ---------------------------------------------------------------------------
// Kernel 2: prep — fused x->fp16 convert + s[t]; 512 CTAs x 16 tokens
//   K in 8 chunks of 128; 8 warps = 8 k16 slices per chunk; M=16 (one tile)
// ---------------------------------------------------------------------------
#define P_PITCH 136
#define PX_STG  (16 * P_PITCH)        // 16 token rows
#define PW_STG  (32 * P_PITCH)        // 32 W23 rows

__global__ void __launch_bounds__(256) s6_prep(const float* __restrict__ x,
                                               const float* __restrict__ b2,
                                               const float* __restrict__ b3) {
    __shared__ __half sX[2][PX_STG];
    __shared__ __half sW[2][PW_STG];
    __shared__ float sU[16][33];

    const int tid = threadIdx.x;
    const int wid = tid >> 5;
    const int lane = tid & 31;
    const int grp = lane >> 2;
    const int qid = lane & 3;
    const int tok0 = blockIdx.x * 16;
    const uint32_t sW_u[2] = { smem_u32(sW[0]), smem_u32(sW[1]) };

    for (int i = tid; i < 16 * 33; i += 256) ((float*)sU)[i] = 0.0f;

    // preload W chunk 0: 32 rows x 16 x 16B chunks = 512 (2 per thread)
#pragma unroll
    for (int j = 0; j < 2; ++j) {
        const int i = tid + j * 256;
        const int row = i >> 4, ch = i & 15;
        cp_async16(sW_u[0] + (uint32_t)(row * P_PITCH + ch * 8) * 2,
                   g_W23h + row * DDIM + ch * 8);
    }
    cp_commit();

    const int t = tid >> 4;            // token row (0..15)
    const int co = (tid & 15) * 8;     // col offset within chunk

    float acc[4][4];
#pragma unroll
    for (int g = 0; g < 4; ++g)
#pragma unroll
        for (int q = 0; q < 4; ++q) acc[g][q] = 0.0f;

    for (int c = 0; c < 8; ++c) {
        const int st = c & 1;
        // convert 8 floats of x -> sX + g_Xh
        const float* src = x + (size_t)(tok0 + t) * DDIM + c * 128 + co;
        float4 v0 = *(const float4*)(src + 0);
        float4 v1 = *(const float4*)(src + 4);
        uint4 pk;
        pk.x = h2_u32(__float22half2_rn(make_float2(v0.x, v0.y)));
        pk.y = h2_u32(__float22half2_rn(make_float2(v0.z, v0.w)));
        pk.z = h2_u32(__float22half2_rn(make_float2(v1.x, v1.y)));
        pk.w = h2_u32(__float22half2_rn(make_float2(v1.z, v1.w)));
        *(uint4*)(&sX[st][t * P_PITCH + co]) = pk;
        *(uint4*)(g_Xh + (size_t)(tok0 + t) * DDIM + c * 128 + co) = pk;

        cp_wait<0>();
        __syncthreads();   // sW[st] ready, sX[st] visible, prior mma done

        if (c < 7) {       // prefetch next W chunk (same 16B-stride layout)
            const int ns = (c + 1) & 1;
#pragma unroll
            for (int j = 0; j < 2; ++j) {
                const int i = tid + j * 256;
                const int row = i >> 4, ch = i & 15;
                cp_async16(sW_u[ns] + (uint32_t)(row * P_PITCH + ch * 8) * 2,
                           g_W23h + row * DDIM + (c + 1) * 128 + ch * 8);
            }
            cp_commit();
        }

        // mma: warp `wid` handles k16 slice wid of the chunk; M=16, N=32
        const int koff = wid * 16 + 2 * qid;
        {
            const __half* p = &sX[st][grp * P_PITCH + koff];
            uint32_t a[4];
            a[0] = *(const uint32_t*)p;
            a[1] = *(const uint32_t*)(p + 8 * P_PITCH);
            a[2] = *(const uint32_t*)(p + 8);
            a[3] = *(const uint32_t*)(p + 8 * P_PITCH + 8);
#pragma unroll
            for (int g = 0; g < 4; ++g) {
                const __half* q = &sW[st][(g * 8 + grp) * P_PITCH + koff];
                uint32_t b[2];
                b[0] = *(const uint32_t*)q;
                b[1] = *(const uint32_t*)(q + 8);
                mma_f16(acc[g], a, b);
            }
        }
        __syncthreads();   // protect sX[st]/sW[st] rewrite
    }

    // cross-warp reduce via smem atomics
#pragma unroll
    for (int g = 0; g < 4; ++g) {
        atomicAdd(&sU[grp][g * 8 + 2 * qid],         acc[g][0]);
        atomicAdd(&sU[grp][g * 8 + 2 * qid + 1],     acc[g][1]);
        atomicAdd(&sU[grp + 8][g * 8 + 2 * qid],     acc[g][2]);
        atomicAdd(&sU[grp + 8][g * 8 + 2 * qid + 1], acc[g][3]);
    }
    __syncthreads();

    if (tid < 16) {
        float s = 0.0f;
#pragma unroll
        for (int n = 0; n < 16; ++n)
            s += (sU[tid][n] + __ldg(b2 + n)) * (sU[tid][n + 16] + __ldg(b3 + n));
        g_s[tok0 + tid] = s;
    }
}

// ---------------------------------------------------------------------------
// Kernel 3: main GEMM — R7 config (128x128, 4 warps @ 64x64, 3 stages)
// ---------------------------------------------------------------------------
__device__ __forceinline__ void g_prefetch(uint32_t smem_base_u, int stage, int kt,
                                           int m0, int n0, int tid) {
    const uint32_t st = smem_base_u + (uint32_t)(stage * G_STAGE_H) * 2;
#pragma unroll
    for (int i = 0; i < 4; ++i) {           // A: 128 rows x 4 x 16B
        const int c = tid + i * GTHREADS;
        const int row = c >> 2, ch = c & 3;
        cp_async16(st + (uint32_t)(row * PITCH_H + ch * 8) * 2,
                   g_Xh + (size_t)(m0 + row) * DDIM + kt * BK + ch * 8);
    }
#pragma unroll
    for (int i = 0; i < 4; ++i) {           // B: 128 rows x 4 x 16B
        const int c = tid + i * GTHREADS;
        const int row = c >> 2, ch = c & 3;
        cp_async16(st + (uint32_t)(A_STAGE_H + row * PITCH_H + ch * 8) * 2,
                   g_Wh + (size_t)(n0 + row) * DDIM + kt * BK + ch * 8);
    }
}

__global__ void __launch_bounds__(GTHREADS, 2) s6_gemm(const float* __restrict__ x,
                                                       const float* __restrict__ b1,
                                                       float* __restrict__ y) {
    extern __shared__ __half smh[];
    const uint32_t sm_u = smem_u32(smh);

    const int tid = threadIdx.x;
    const int wid = tid >> 5;
    const int lane = tid & 31;
    const int grp = lane >> 2;
    const int qid = lane & 3;
    const int wm = wid & 1;      // 2 warps along M (64 each)
    const int wn = wid >> 1;     // 2 warps along N (64 each)
    const int m0 = blockIdx.y * BM;
    const int n0 = blockIdx.x * BN;

    const uint32_t aIdx = (uint32_t)((wm * 64 + (lane & 15)) * PITCH_H + (lane >> 4) * 8);
    const uint32_t bIdx = (uint32_t)(A_STAGE_H +
        (wn * 64 + ((lane >> 4) & 1) * 8 + (lane & 7)) * PITCH_H + ((lane >> 3) & 1) * 8);

    float acc[4][8][4];
#pragma unroll
    for (int f = 0; f < 4; ++f)
#pragma unroll
        for (int g = 0; g < 8; ++g)
#pragma unroll
            for (int q = 0; q < 4; ++q) acc[f][g][q] = 0.0f;

    g_prefetch(sm_u, 0, 0, m0, n0, tid);
    cp_commit();
    g_prefetch(sm_u, 1, 1, m0, n0, tid);
    cp_commit();

    for (int kt = 0; kt < NKIT; ++kt) {
        const int s = kt % STAGES;
        cp_wait<1>();
        __syncthreads();

        const int pf = kt + 2;
        if (pf < NKIT) g_prefetch(sm_u, pf % STAGES, pf, m0, n0, tid);
        cp_commit();

        const uint32_t stg = sm_u + (uint32_t)(s * G_STAGE_H) * 2;
#pragma unroll
        for (int ks = 0; ks < 2; ++ks) {
            uint32_t af[4][4], bf[8][2];
#pragma unroll
            for (int f = 0; f < 4; ++f)
                ldmx4(af[f], stg + (aIdx + (uint32_t)(f * 16 * PITCH_H + ks * 16)) * 2);
#pragma unroll
            for (int h = 0; h < 4; ++h) {
                uint32_t bq[4];
                ldmx4(bq, stg + (bIdx + (uint32_t)(h * 16 * PITCH_H + ks * 16)) * 2);
                bf[2 * h][0]     = bq[0];
                bf[2 * h][1]     = bq[1];
                bf[2 * h + 1][0] = bq[2];
                bf[2 * h + 1][1] = bq[3];
            }
#pragma unroll
            for (int f = 0; f < 4; ++f)
#pragma unroll
                for (int g = 0; g < 8; ++g)
                    mma_f16(acc[f][g], af[f], bf[g]);
        }
    }

    // fused epilogue: y = x * softplus(acc + b1) * s
#pragma unroll
    for (int f = 0; f < 4; ++f) {
        const int r0 = m0 + wm * 64 + f * 16 + grp;
        const int r1 = r0 + 8;
        const float s0 = __ldg(g_s + r0);
        const float s1 = __ldg(g_s + r1);
        const float* xr0 = x + (size_t)r0 * DDIM;
        const float* xr1 = x + (size_t)r1 * DDIM;
        float* yr0 = y + (size_t)r0 * DDIM;
        float* yr1 = y + (size_t)r1 * DDIM;
#pragma unroll
        for (int g = 0; g < 8; ++g) {
            const int c = n0 + wn * 64 + g * 8 + 2 * qid;
            const float2 bv = *(const float2*)(b1 + c);
            const float2 x0 = *(const float2*)(xr0 + c);
            const float2 x1 = *(const float2*)(xr1 + c);
            float2 o0, o1;
            o0.x = x0.x * softplus_f(acc[f][g][0] + bv.x) * s0;
            o0.y = x0.y * softplus_f(acc[f][g][1] + bv.y) * s0;
            o1.x = x1.x * softplus_f(acc[f][g][2] + bv.x) * s1;
            o1.y = x1.y * softplus_f(acc[f][g][3] + bv.y) * s1;
            *(float2*)(yr0 + c) = o0;
            *(float2*)(yr1 + c) = o1;
        }
    }
}

// ---------------------------------------------------------------------------
// Launch
// ---------------------------------------------------------------------------
extern "C" void kernel_launch(void* const* d_in, const int* in_sizes, int n_in,
                              void* d_out, int out_size) {
    const float* x  = (const float*)d_in[0];
    const float* W1 = (const float*)d_in[1];
    const float* b1 = (const float*)d_in[2];
    const float* W2 = (const float*)d_in[3];
    const float* b2 = (const float*)d_in[4];
    const float* W3 = (const float*)d_in[5];
    const float* b3 = (const float*)d_in[6];
    float* y = (float*)d_out;

    s6_pack<<<1024 + 32, dim3(32, 32)>>>(W1, W2, W3);
    s6_prep<<<NTOK / 16, 256>>>(x, b2, b3);

    cudaFuncSetAttribute(s6_gemm, cudaFuncAttributeMaxDynamicSharedMemorySize, G_SMEM_BYTES);
    s6_gemm<<<dim3(DDIM / BN, NTOK / BM), GTHREADS, G_SMEM_BYTES>>>(x, b1, y);
}

// round 13
// speedup vs baseline: 1.3151x; 1.1138x over previous
#include <cuda_runtime.h>
#include <cuda_fp16.h>
#include <cstdint>

// ============================================================================
// S6 forward, reduced:
//   y[t,d] = x[t,d] * softplus(U1[t,d] + b1[d]) * s[t]
//   s[t]   = sum_n (U2[t,n]+b2[n]) * (U3[t,n]+b3[n])
// Pipeline (fp16 mma.sync, fp32 accum; base sm_103 ISA — no tcgen05):
//   1. pack:  W1 -> g_W1h [k][n] fp16 (NO transpose — gemm uses ldmatrix.trans)
//             W2|W3 -> g_W23h [32][k]
//   2. prep:  x -> g_Xh fp16 AND g_s[t]  (512 CTAs x 16 tokens)
//   3. gemm:  128x128 CTA, 4 warps @ 64x64, A ldmatrix / B ldmatrix.trans,
//             3-stage cp.async, fused epilogue -> y
// ============================================================================

#define NTOK   8192
#define DDIM   1024

#define BM     128
#define BN     128
#define BK     32
#define NKIT   (DDIM / BK)   // 32
#define GTHREADS 128         // 4 warps, 2x2 warp grid, 64x64 per warp

#define PITCH_H   40         // A smem row pitch (halves) = 80B
#define B_PITCH_H 136        // B smem row pitch (halves) = 272B; trans-ldm conflict-free
#define A_STAGE_H (BM * PITCH_H)               // 5120 halves
#define B_STAGE_H (BK * B_PITCH_H)             // 4352 halves
#define G_STAGE_H (A_STAGE_H + B_STAGE_H)      // 9472
#define STAGES    3
#define G_SMEM_BYTES (STAGES * G_STAGE_H * 2)  // 56832

__device__ __half g_W1h[(size_t)DDIM * DDIM];  // W1, [k][n], fp16, 2 MB
__device__ __half g_W23h[32 * DDIM];           // [n][k]: n<16 W2 col, n>=16 W3 col
__device__ __half g_Xh[(size_t)NTOK * DDIM];   // x fp16, 16.8 MB
__device__ float  g_s[NTOK];

// ---------------------------------------------------------------------------
// helpers
// ---------------------------------------------------------------------------
__device__ __forceinline__ uint32_t smem_u32(const void* p) {
    uint32_t a;
    asm("{ .reg .u64 t; cvta.to.shared.u64 t, %1; cvt.u32.u64 %0, t; }" : "=r"(a) : "l"(p));
    return a;
}
__device__ __forceinline__ uint32_t h2_u32(__half2 h) {
    union { __half2 h; uint32_t u; } cvt;
    cvt.h = h;
    return cvt.u;
}
__device__ __forceinline__ void cp_async16(uint32_t dst, const void* src) {
    asm volatile("cp.async.cg.shared.global [%0], [%1], 16;" :: "r"(dst), "l"(src) : "memory");
}
__device__ __forceinline__ void cp_commit() {
    asm volatile("cp.async.commit_group;" ::: "memory");
}
template <int N>
__device__ __forceinline__ void cp_wait() {
    asm volatile("cp.async.wait_group %0;" :: "n"(N) : "memory");
}
__device__ __forceinline__ void ldmx4(uint32_t* r, uint32_t addr) {
    asm volatile("ldmatrix.sync.aligned.m8n8.x4.shared.b16 {%0,%1,%2,%3}, [%4];"
        : "=r"(r[0]), "=r"(r[1]), "=r"(r[2]), "=r"(r[3]) : "r"(addr));
}
__device__ __forceinline__ void ldmx4t(uint32_t* r, uint32_t addr) {
    asm volatile("ldmatrix.sync.aligned.m8n8.x4.trans.shared.b16 {%0,%1,%2,%3}, [%4];"
        : "=r"(r[0]), "=r"(r[1]), "=r"(r[2]), "=r"(r[3]) : "r"(addr));
}
__device__ __forceinline__ void mma_f16(float* c, const uint32_t* a, const uint32_t* b) {
    asm volatile(
        "mma.sync.aligned.m16n8k16.row.col.f32.f16.f16.f32 "
        "{%0,%1,%2,%3}, {%4,%5,%6,%7}, {%8,%9}, {%0,%1,%2,%3};"
        : "+f"(c[0]), "+f"(c[1]), "+f"(c[2]), "+f"(c[3])
        : "r"(a[0]), "r"(a[1]), "r"(a[2]), "r"(a[3]), "r"(b[0]), "r"(b[1]));
}
__device__ __forceinline__ float softplus_f(float z) {
    return fmaxf(z, 0.0f) + __logf(1.0f + __expf(-fabsf(z)));
}

// ---------------------------------------------------------------------------
// Kernel 1: pack — blocks [0,1024): W1 fp32->fp16 copy (vectorized, no
//           transpose); blocks [1024,1056): W23 gather
// ---------------------------------------------------------------------------
__global__ void __launch_bounds__(256) s6_pack(const float* __restrict__ W1,
                                               const float* __restrict__ W2,
                                               const float* __restrict__ W3) {
    const int bid = blockIdx.x;
    const int tid = threadIdx.x;
    if (bid < 1024) {
        const size_t i4 = (size_t)bid * 256 + tid;     // float4 index, 262144 total
        const float4 v = ((const float4*)W1)[i4];
        uint2 pk;
        pk.x = h2_u32(__float22half2_rn(make_float2(v.x, v.y)));
        pk.y = h2_u32(__float22half2_rn(make_float2(v.z, v.w)));
        ((uint2*)g_W1h)[i4] = pk;
    } else {
        const int base = (bid - 1024) * 1024 + tid * 4;   // 4 consecutive k, same n
        const int n = base >> 10;
        const int k = base & 1023;
        uint2 pk;
        if (n < 16) {
            float a = W2[(size_t)k * 16 + n],       b = W2[(size_t)(k + 1) * 16 + n];
            float c = W2[(size_t)(k + 2) * 16 + n], d = W2[(size_t)(k + 3) * 16 + n];
            pk.x = h2_u32(__float22half2_rn(make_float2(a, b)));
            pk.y = h2_u32(__float22half2_rn(make_float2(c, d)));
        } else {
            const int nn = n - 16;
            float a = W3[(size_t)k * 16 + nn],       b = W3[(size_t)(k + 1) * 16 + nn];
            float c = W3[(size_t)(k + 2) * 16 + nn], d = W3[(size_t)(k + 3) * 16 + nn];
            pk.x = h2_u32(__float22half2_rn(make_float2(a, b)));
            pk.y = h2_u32(__float22half2_rn(make_float2(c, d)));
        }
        *(uint2*)(g_W23h + n * DDIM + k) = pk;
    }
}

// ---------------------------------------------------------------------------
// Kernel 2: prep — fused x->fp16 convert + s[t]; 512 CTAs x 16 tokens
// ---------------------------------------------------------------------------
#define P_PITCH 136
#define PX_STG  (16 * P_PITCH)
#define PW_STG  (32 * P_PITCH)

__global__ void __launch_bounds__(256) s6_prep(const float* __restrict__ x,
                                               const float* __restrict__ b2,
                                               const float* __restrict__ b3) {
    __shared__ __half sX[2][PX_STG];
    __shared__ __half sW[2][PW_STG];
    __shared__ float sU[16][33];

    const int tid = threadIdx.x;
    const int wid = tid >> 5;
    const int lane = tid & 31;
    const int grp = lane >> 2;
    const int qid = lane & 3;
    const int tok0 = blockIdx.x * 16;
    const uint32_t sW_u[2] = { smem_u32(sW[0]), smem_u32(sW[1]) };

    for (int i = tid; i < 16 * 33; i += 256) ((float*)sU)[i] = 0.0f;

#pragma unroll
    for (int j = 0; j < 2; ++j) {
        const int i = tid + j * 256;
        const int row = i >> 4, ch = i & 15;
        cp_async16(sW_u[0] + (uint32_t)(row * P_PITCH + ch * 8) * 2,
                   g_W23h + row * DDIM + ch * 8);
    }
    cp_commit();

    const int t = tid >> 4;
    const int co = (tid & 15) * 8;

    float acc[4][4];
#pragma unroll
    for (int g = 0; g < 4; ++g)
#pragma unroll
        for (int q = 0; q < 4; ++q) acc[g][q] = 0.0f;

    for (int c = 0; c < 8; ++c) {
        const int st = c & 1;
        const float* src = x + (size_t)(tok0 + t) * DDIM + c * 128 + co;
        float4 v0 = *(const float4*)(src + 0);
        float4 v1 = *(const float4*)(src + 4);
        uint4 pk;
        pk.x = h2_u32(__float22half2_rn(make_float2(v0.x, v0.y)));
        pk.y = h2_u32(__float22half2_rn(make_float2(v0.z, v0.w)));
        pk.z = h2_u32(__float22half2_rn(make_float2(v1.x, v1.y)));
        pk.w = h2_u32(__float22half2_rn(make_float2(v1.z, v1.w)));
        *(uint4*)(&sX[st][t * P_PITCH + co]) = pk;
        *(uint4*)(g_Xh + (size_t)(tok0 + t) * DDIM + c * 128 + co) = pk;

        cp_wait<0>();
        __syncthreads();

        if (c < 7) {
            const int ns = (c + 1) & 1;
#pragma unroll
            for (int j = 0; j < 2; ++j) {
                const int i = tid + j * 256;
                const int row = i >> 4, ch = i & 15;
                cp_async16(sW_u[ns] + (uint32_t)(row * P_PITCH + ch * 8) * 2,
                           g_W23h + row * DDIM + (c + 1) * 128 + ch * 8);
            }
            cp_commit();
        }

        const int koff = wid * 16 + 2 * qid;
        {
            const __half* p = &sX[st][grp * P_PITCH + koff];
            uint32_t a[4];
            a[0] = *(const uint32_t*)p;
            a[1] = *(const uint32_t*)(p + 8 * P_PITCH);
            a[2] = *(const uint32_t*)(p + 8);
            a[3] = *(const uint32_t*)(p + 8 * P_PITCH + 8);
#pragma unroll
            for (int g = 0; g < 4; ++g) {
                const __half* q = &sW[st][(g * 8 + grp) * P_PITCH + koff];
                uint32_t b[2];
                b[0] = *(const uint32_t*)q;
                b[1] = *(const uint32_t*)(q + 8);
                mma_f16(acc[g], a, b);
            }
        }
        __syncthreads();
    }

#pragma unroll
    for (int g = 0; g < 4; ++g) {
        atomicAdd(&sU[grp][g * 8 + 2 * qid],         acc[g][0]);
        atomicAdd(&sU[grp][g * 8 + 2 * qid + 1],     acc[g][1]);
        atomicAdd(&sU[grp + 8][g * 8 + 2 * qid],     acc[g][2]);
        atomicAdd(&sU[grp + 8][g * 8 + 2 * qid + 1], acc[g][3]);
    }
    __syncthreads();

    if (tid < 16) {
        float s = 0.0f;
#pragma unroll
        for (int n = 0; n < 16; ++n)
            s += (sU[tid][n] + __ldg(b2 + n)) * (sU[tid][n + 16] + __ldg(b3 + n));
        g_s[tok0 + tid] = s;
    }
}

// ---------------------------------------------------------------------------
// Kernel 3: main GEMM — A ldmatrix from [m][k], B ldmatrix.trans from [k][n]
// ---------------------------------------------------------------------------
__device__ __forceinline__ void g_prefetch(uint32_t smem_base_u, int stage, int kt,
                                           int m0, int n0, int tid) {
    const uint32_t st = smem_base_u + (uint32_t)(stage * G_STAGE_H) * 2;
#pragma unroll
    for (int i = 0; i < 4; ++i) {           // A: 128 rows x 4 x 16B
        const int c = tid + i * GTHREADS;
        const int row = c >> 2, ch = c & 3;
        cp_async16(st + (uint32_t)(row * PITCH_H + ch * 8) * 2,
                   g_Xh + (size_t)(m0 + row) * DDIM + kt * BK + ch * 8);
    }
#pragma unroll
    for (int i = 0; i < 4; ++i) {           // B: 32 k-rows x 16 x 16B
        const int c = tid + i * GTHREADS;
        const int row = c >> 4, ch = c & 15;
        cp_async16(st + (uint32_t)(A_STAGE_H + row * B_PITCH_H + ch * 8) * 2,
                   g_W1h + (size_t)(kt * BK + row) * DDIM + n0 + ch * 8);
    }
}

__global__ void __launch_bounds__(GTHREADS, 2) s6_gemm(const float* __restrict__ x,
                                                       const float* __restrict__ b1,
                                                       float* __restrict__ y) {
    extern __shared__ __half smh[];
    const uint32_t sm_u = smem_u32(smh);

    const int tid = threadIdx.x;
    const int wid = tid >> 5;
    const int lane = tid & 31;
    const int grp = lane >> 2;
    const int qid = lane & 3;
    const int wm = wid & 1;      // 2 warps along M (64 each)
    const int wn = wid >> 1;     // 2 warps along N (64 each)
    const int m0 = blockIdx.y * BM;
    const int n0 = blockIdx.x * BN;

    // A: non-trans ldmatrix from [m][k]
    const uint32_t aIdx = (uint32_t)((wm * 64 + (lane & 15)) * PITCH_H + (lane >> 4) * 8);
    // B: trans ldmatrix from [k][n]: lane supplies k-row address of its matrix
    //   matrix = lane>>3: bit0 -> +8 k, bit1 -> +8 n
    const uint32_t bIdx = (uint32_t)(A_STAGE_H +
        (((lane >> 3) & 1) * 8 + (lane & 7)) * B_PITCH_H + ((lane >> 4) & 1) * 8 + wn * 64);

    float acc[4][8][4];
#pragma unroll
    for (int f = 0; f < 4; ++f)
#pragma unroll
        for (int g = 0; g < 8; ++g)
#pragma unroll
            for (int q = 0; q < 4; ++q) acc[f][g][q] = 0.0f;

    g_prefetch(sm_u, 0, 0, m0, n0, tid);
    cp_commit();
    g_prefetch(sm_u, 1, 1, m0, n0, tid);
    cp_commit();

    for (int kt = 0; kt < NKIT; ++kt) {
        const int s = kt % STAGES;
        cp_wait<1>();
        __syncthreads();

        const int pf = kt + 2;
        if (pf < NKIT) g_prefetch(sm_u, pf % STAGES, pf, m0, n0, tid);
        cp_commit();

        const uint32_t stg = sm_u + (uint32_t)(s * G_STAGE_H) * 2;
#pragma unroll
        for (int ks = 0; ks < 2; ++ks) {
            uint32_t af[4][4], bf[8][2];
#pragma unroll
            for (int f = 0; f < 4; ++f)
                ldmx4(af[f], stg + (aIdx + (uint32_t)(f * 16 * PITCH_H + ks * 16)) * 2);
#pragma unroll
            for (int h = 0; h < 4; ++h) {
                uint32_t bq[4];
                ldmx4t(bq, stg + (bIdx + (uint32_t)(ks * 16 * B_PITCH_H + h * 16)) * 2);
                bf[2 * h][0]     = bq[0];   // (k lo, n lo)
                bf[2 * h][1]     = bq[1];   // (k hi, n lo)
                bf[2 * h + 1][0] = bq[2];   // (k lo, n hi)
                bf[2 * h + 1][1] = bq[3];   // (k hi, n hi)
            }
#pragma unroll
            for (int f = 0; f < 4; ++f)
#pragma unroll
                for (int g = 0; g < 8; ++g)
                    mma_f16(acc[f][g], af[f], bf[g]);
        }
    }

    // fused epilogue: y = x * softplus(acc + b1) * s
#pragma unroll
    for (int f = 0; f < 4; ++f) {
        const int r0 = m0 + wm * 64 + f * 16 + grp;
        const int r1 = r0 + 8;
        const float s0 = __ldg(g_s + r0);
        const float s1 = __ldg(g_s + r1);
        const float* xr0 = x + (size_t)r0 * DDIM;
        const float* xr1 = x + (size_t)r1 * DDIM;
        float* yr0 = y + (size_t)r0 * DDIM;
        float* yr1 = y + (size_t)r1 * DDIM;
#pragma unroll
        for (int g = 0; g < 8; ++g) {
            const int c = n0 + wn * 64 + g * 8 + 2 * qid;
            const float2 bv = *(const float2*)(b1 + c);
            const float2 x0 = *(const float2*)(xr0 + c);
            const float2 x1 = *(const float2*)(xr1 + c);
            float2 o0, o1;
            o0.x = x0.x * softplus_f(acc[f][g][0] + bv.x) * s0;
            o0.y = x0.y * softplus_f(acc[f][g][1] + bv.y) * s0;
            o1.x = x1.x * softplus_f(acc[f][g][2] + bv.x) * s1;
            o1.y = x1.y * softplus_f(acc[f][g][3] + bv.y) * s1;
            *(float2*)(yr0 + c) = o0;
            *(float2*)(yr1 + c) = o1;
        }
    }
}

// ---------------------------------------------------------------------------
// Launch
// ---------------------------------------------------------------------------
extern "C" void kernel_launch(void* const* d_in, const int* in_sizes, int n_in,
                              void* d_out, int out_size) {
    const float* x  = (const float*)d_in[0];
    const float* W1 = (const float*)d_in[1];
    const float* b1 = (const float*)d_in[2];
    const float* W2 = (const float*)d_in[3];
    const float* b2 = (const float*)d_in[4];
    const float* W3 = (const float*)d_in[5];
    const float* b3 = (const float*)d_in[6];
    float* y = (float*)d_out;

    s6_pack<<<1024 + 32, 256>>>(W1, W2, W3);
    s6_prep<<<NTOK / 16, 256>>>(x, b2, b3);

    cudaFuncSetAttribute(s6_gemm, cudaFuncAttributeMaxDynamicSharedMemorySize, G_SMEM_BYTES);
    s6_gemm<<<dim3(DDIM / BN, NTOK / BM), GTHREADS, G_SMEM_BYTES>>>(x, b1, y);
}

// round 14
// speedup vs baseline: 1.3211x; 1.0045x over previous
#include <cuda_runtime.h>
#include <cuda_fp16.h>
#include <cstdint>

// ============================================================================
// S6 forward, reduced:
//   y[t,d] = x[t,d] * softplus(U1[t,d] + b1[d]) * s[t]
//   s[t]   = sum_n (U2[t,n]+b2[n]) * (U3[t,n]+b3[n])
// Pipeline (fp16 mma.sync, fp32 accum; base sm_103 ISA — no tcgen05):
//   1. pack_w23: W2|W3 -> g_W23h [32][k]   (tiny, 32 CTAs)
//   2. prep+packW1 (ONE kernel): blocks [0,512) = x->fp16 + s[t];
//      blocks [512,768) = W1 fp32->fp16 copy (overlapped with prep)
//   3. gemm: 128x128 CTA, 4 warps @ 64x64, A ldmatrix / B ldmatrix.trans,
//            3-stage cp.async, fused epilogue -> y
// ============================================================================

#define NTOK   8192
#define DDIM   1024

#define BM     128
#define BN     128
#define BK     32
#define NKIT   (DDIM / BK)   // 32
#define GTHREADS 128         // 4 warps, 2x2 warp grid, 64x64 per warp

#define PITCH_H   40         // A smem row pitch (halves) = 80B
#define B_PITCH_H 136        // B smem row pitch (halves) = 272B; trans-ldm conflict-free
#define A_STAGE_H (BM * PITCH_H)               // 5120 halves
#define B_STAGE_H (BK * B_PITCH_H)             // 4352 halves
#define G_STAGE_H (A_STAGE_H + B_STAGE_H)      // 9472
#define STAGES    3
#define G_SMEM_BYTES (STAGES * G_STAGE_H * 2)  // 56832

#define PREP_BLOCKS 512
#define COPY_BLOCKS 256       // 262144 float4 / 1024 per block

__device__ __half g_W1h[(size_t)DDIM * DDIM];  // W1, [k][n], fp16, 2 MB
__device__ __half g_W23h[32 * DDIM];           // [n][k]: n<16 W2 col, n>=16 W3 col
__device__ __half g_Xh[(size_t)NTOK * DDIM];   // x fp16, 16.8 MB
__device__ float  g_s[NTOK];

// ---------------------------------------------------------------------------
// helpers
// ---------------------------------------------------------------------------
__device__ __forceinline__ uint32_t smem_u32(const void* p) {
    uint32_t a;
    asm("{ .reg .u64 t; cvta.to.shared.u64 t, %1; cvt.u32.u64 %0, t; }" : "=r"(a) : "l"(p));
    return a;
}
__device__ __forceinline__ uint32_t h2_u32(__half2 h) {
    union { __half2 h; uint32_t u; } cvt;
    cvt.h = h;
    return cvt.u;
}
__device__ __forceinline__ void cp_async16(uint32_t dst, const void* src) {
    asm volatile("cp.async.cg.shared.global [%0], [%1], 16;" :: "r"(dst), "l"(src) : "memory");
}
__device__ __forceinline__ void cp_commit() {
    asm volatile("cp.async.commit_group;" ::: "memory");
}
template <int N>
__device__ __forceinline__ void cp_wait() {
    asm volatile("cp.async.wait_group %0;" :: "n"(N) : "memory");
}
__device__ __forceinline__ void ldmx4(uint32_t* r, uint32_t addr) {
    asm volatile("ldmatrix.sync.aligned.m8n8.x4.shared.b16 {%0,%1,%2,%3}, [%4];"
        : "=r"(r[0]), "=r"(r[1]), "=r"(r[2]), "=r"(r[3]) : "r"(addr));
}
__device__ __forceinline__ void ldmx4t(uint32_t* r, uint32_t addr) {
    asm volatile("ldmatrix.sync.aligned.m8n8.x4.trans.shared.b16 {%0,%1,%2,%3}, [%4];"
        : "=r"(r[0]), "=r"(r[1]), "=r"(r[2]), "=r"(r[3]) : "r"(addr));
}
__device__ __forceinline__ void mma_f16(float* c, const uint32_t* a, const uint32_t* b) {
    asm volatile(
        "mma.sync.aligned.m16n8k16.row.col.f32.f16.f16.f32 "
        "{%0,%1,%2,%3}, {%4,%5,%6,%7}, {%8,%9}, {%0,%1,%2,%3};"
        : "+f"(c[0]), "+f"(c[1]), "+f"(c[2]), "+f"(c[3])
        : "r"(a[0]), "r"(a[1]), "r"(a[2]), "r"(a[3]), "r"(b[0]), "r"(b[1]));
}
__device__ __forceinline__ float softplus_f(float z) {
    return fmaxf(z, 0.0f) + __logf(1.0f + __expf(-fabsf(z)));
}

// ---------------------------------------------------------------------------
// Kernel 1: pack_w23 — W2|W3 gather (32 CTAs)
// ---------------------------------------------------------------------------
__global__ void __launch_bounds__(256) s6_pack_w23(const float* __restrict__ W2,
                                                   const float* __restrict__ W3) {
    const int base = blockIdx.x * 1024 + threadIdx.x * 4;   // 4 consecutive k, same n
    const int n = base >> 10;
    const int k = base & 1023;
    uint2 pk;
    if (n < 16) {
        float a = W2[(size_t)k * 16 + n],       b = W2[(size_t)(k + 1) * 16 + n];
        float c = W2[(size_t)(k + 2) * 16 + n], d = W2[(size_t)(k + 3) * 16 + n];
        pk.x = h2_u32(__float22half2_rn(make_float2(a, b)));
        pk.y = h2_u32(__float22half2_rn(make_float2(c, d)));
    } else {
        const int nn = n - 16;
        float a = W3[(size_t)k * 16 + nn],       b = W3[(size_t)(k + 1) * 16 + nn];
        float c = W3[(size_t)(k + 2) * 16 + nn], d = W3[(size_t)(k + 3) * 16 + nn];
        pk.x = h2_u32(__float22half2_rn(make_float2(a, b)));
        pk.y = h2_u32(__float22half2_rn(make_float2(c, d)));
    }
    *(uint2*)(g_W23h + n * DDIM + k) = pk;
}

// ---------------------------------------------------------------------------
// Kernel 2: prep + W1 pack, one launch.
//   blocks [0,512):   fused x->fp16 convert + s[t], 16 tokens each
//   blocks [512,768): W1 fp32->fp16 copy, 4 float4 per thread
// ---------------------------------------------------------------------------
#define P_PITCH 136
#define PX_STG  (16 * P_PITCH)
#define PW_STG  (32 * P_PITCH)

__global__ void __launch_bounds__(256) s6_prep(const float* __restrict__ x,
                                               const float* __restrict__ W1,
                                               const float* __restrict__ b2,
                                               const float* __restrict__ b3) {
    __shared__ __half sX[2][PX_STG];
    __shared__ __half sW[2][PW_STG];
    __shared__ float sU[16][33];

    const int tid = threadIdx.x;

    if (blockIdx.x >= PREP_BLOCKS) {
        // ---- W1 copy path (overlaps prep blocks) ----
        const int rel = blockIdx.x - PREP_BLOCKS;
#pragma unroll
        for (int i = 0; i < 4; ++i) {
            const size_t i4 = (size_t)rel * 1024 + i * 256 + tid;
            const float4 v = ((const float4*)W1)[i4];
            uint2 pk;
            pk.x = h2_u32(__float22half2_rn(make_float2(v.x, v.y)));
            pk.y = h2_u32(__float22half2_rn(make_float2(v.z, v.w)));
            ((uint2*)g_W1h)[i4] = pk;
        }
        return;
    }

    // ---- prep path ----
    const int wid = tid >> 5;
    const int lane = tid & 31;
    const int grp = lane >> 2;
    const int qid = lane & 3;
    const int tok0 = blockIdx.x * 16;
    const uint32_t sW_u[2] = { smem_u32(sW[0]), smem_u32(sW[1]) };

    for (int i = tid; i < 16 * 33; i += 256) ((float*)sU)[i] = 0.0f;

#pragma unroll
    for (int j = 0; j < 2; ++j) {
        const int i = tid + j * 256;
        const int row = i >> 4, ch = i & 15;
        cp_async16(sW_u[0] + (uint32_t)(row * P_PITCH + ch * 8) * 2,
                   g_W23h + row * DDIM + ch * 8);
    }
    cp_commit();

    const int t = tid >> 4;
    const int co = (tid & 15) * 8;

    float acc[4][4];
#pragma unroll
    for (int g = 0; g < 4; ++g)
#pragma unroll
        for (int q = 0; q < 4; ++q) acc[g][q] = 0.0f;

    for (int c = 0; c < 8; ++c) {
        const int st = c & 1;
        const float* src = x + (size_t)(tok0 + t) * DDIM + c * 128 + co;
        float4 v0 = *(const float4*)(src + 0);
        float4 v1 = *(const float4*)(src + 4);
        uint4 pk;
        pk.x = h2_u32(__float22half2_rn(make_float2(v0.x, v0.y)));
        pk.y = h2_u32(__float22half2_rn(make_float2(v0.z, v0.w)));
        pk.z = h2_u32(__float22half2_rn(make_float2(v1.x, v1.y)));
        pk.w = h2_u32(__float22half2_rn(make_float2(v1.z, v1.w)));
        *(uint4*)(&sX[st][t * P_PITCH + co]) = pk;
        *(uint4*)(g_Xh + (size_t)(tok0 + t) * DDIM + c * 128 + co) = pk;

        cp_wait<0>();
        __syncthreads();

        if (c < 7) {
            const int ns = (c + 1) & 1;
#pragma unroll
            for (int j = 0; j < 2; ++j) {
                const int i = tid + j * 256;
                const int row = i >> 4, ch = i & 15;
                cp_async16(sW_u[ns] + (uint32_t)(row * P_PITCH + ch * 8) * 2,
                           g_W23h + row * DDIM + (c + 1) * 128 + ch * 8);
            }
            cp_commit();
        }

        const int koff = wid * 16 + 2 * qid;
        {
            const __half* p = &sX[st][grp * P_PITCH + koff];
            uint32_t a[4];
            a[0] = *(const uint32_t*)p;
            a[1] = *(const uint32_t*)(p + 8 * P_PITCH);
            a[2] = *(const uint32_t*)(p + 8);
            a[3] = *(const uint32_t*)(p + 8 * P_PITCH + 8);
#pragma unroll
            for (int g = 0; g < 4; ++g) {
                const __half* q = &sW[st][(g * 8 + grp) * P_PITCH + koff];
                uint32_t b[2];
                b[0] = *(const uint32_t*)q;
                b[1] = *(const uint32_t*)(q + 8);
                mma_f16(acc[g], a, b);
            }
        }
        __syncthreads();
    }

#pragma unroll
    for (int g = 0; g < 4; ++g) {
        atomicAdd(&sU[grp][g * 8 + 2 * qid],         acc[g][0]);
        atomicAdd(&sU[grp][g * 8 + 2 * qid + 1],     acc[g][1]);
        atomicAdd(&sU[grp + 8][g * 8 + 2 * qid],     acc[g][2]);
        atomicAdd(&sU[grp + 8][g * 8 + 2 * qid + 1], acc[g][3]);
    }
    __syncthreads();

    if (tid < 16) {
        float s = 0.0f;
#pragma unroll
        for (int n = 0; n < 16; ++n)
            s += (sU[tid][n] + __ldg(b2 + n)) * (sU[tid][n + 16] + __ldg(b3 + n));
        g_s[tok0 + tid] = s;
    }
}

// ---------------------------------------------------------------------------
// Kernel 3: main GEMM — A ldmatrix from [m][k], B ldmatrix.trans from [k][n]
// ---------------------------------------------------------------------------
__device__ __forceinline__ void g_prefetch(uint32_t smem_base_u, int stage, int kt,
                                           int m0, int n0, int tid) {
    const uint32_t st = smem_base_u + (uint32_t)(stage * G_STAGE_H) * 2;
#pragma unroll
    for (int i = 0; i < 4; ++i) {           // A: 128 rows x 4 x 16B
        const int c = tid + i * GTHREADS;
        const int row = c >> 2, ch = c & 3;
        cp_async16(st + (uint32_t)(row * PITCH_H + ch * 8) * 2,
                   g_Xh + (size_t)(m0 + row) * DDIM + kt * BK + ch * 8);
    }
#pragma unroll
    for (int i = 0; i < 4; ++i) {           // B: 32 k-rows x 16 x 16B
        const int c = tid + i * GTHREADS;
        const int row = c >> 4, ch = c & 15;
        cp_async16(st + (uint32_t)(A_STAGE_H + row * B_PITCH_H + ch * 8) * 2,
                   g_W1h + (size_t)(kt * BK + row) * DDIM + n0 + ch * 8);
    }
}

__global__ void __launch_bounds__(GTHREADS, 2) s6_gemm(const float* __restrict__ x,
                                                       const float* __restrict__ b1,
                                                       float* __restrict__ y) {
    extern __shared__ __half smh[];
    const uint32_t sm_u = smem_u32(smh);

    const int tid = threadIdx.x;
    const int wid = tid >> 5;
    const int lane = tid & 31;
    const int grp = lane >> 2;
    const int qid = lane & 3;
    const int wm = wid & 1;      // 2 warps along M (64 each)
    const int wn = wid >> 1;     // 2 warps along N (64 each)
    const int m0 = blockIdx.y * BM;
    const int n0 = blockIdx.x * BN;

    const uint32_t aIdx = (uint32_t)((wm * 64 + (lane & 15)) * PITCH_H + (lane >> 4) * 8);
    const uint32_t bIdx = (uint32_t)(A_STAGE_H +
        (((lane >> 3) & 1) * 8 + (lane & 7)) * B_PITCH_H + ((lane >> 4) & 1) * 8 + wn * 64);

    float acc[4][8][4];
#pragma unroll
    for (int f = 0; f < 4; ++f)
#pragma unroll
        for (int g = 0; g < 8; ++g)
#pragma unroll
            for (int q = 0; q < 4; ++q) acc[f][g][q] = 0.0f;

    g_prefetch(sm_u, 0, 0, m0, n0, tid);
    cp_commit();
    g_prefetch(sm_u, 1, 1, m0, n0, tid);
    cp_commit();

    for (int kt = 0; kt < NKIT; ++kt) {
        const int s = kt % STAGES;
        cp_wait<1>();
        __syncthreads();

        const int pf = kt + 2;
        if (pf < NKIT) g_prefetch(sm_u, pf % STAGES, pf, m0, n0, tid);
        cp_commit();

        const uint32_t stg = sm_u + (uint32_t)(s * G_STAGE_H) * 2;
#pragma unroll
        for (int ks = 0; ks < 2; ++ks) {
            uint32_t af[4][4], bf[8][2];
#pragma unroll
            for (int f = 0; f < 4; ++f)
                ldmx4(af[f], stg + (aIdx + (uint32_t)(f * 16 * PITCH_H + ks * 16)) * 2);
#pragma unroll
            for (int h = 0; h < 4; ++h) {
                uint32_t bq[4];
                ldmx4t(bq, stg + (bIdx + (uint32_t)(ks * 16 * B_PITCH_H + h * 16)) * 2);
                bf[2 * h][0]     = bq[0];   // (k lo, n lo)
                bf[2 * h][1]     = bq[1];   // (k hi, n lo)
                bf[2 * h + 1][0] = bq[2];   // (k lo, n hi)
                bf[2 * h + 1][1] = bq[3];   // (k hi, n hi)
            }
#pragma unroll
            for (int f = 0; f < 4; ++f)
#pragma unroll
                for (int g = 0; g < 8; ++g)
                    mma_f16(acc[f][g], af[f], bf[g]);
        }
    }

    // fused epilogue: y = x * softplus(acc + b1) * s
#pragma unroll
    for (int f = 0; f < 4; ++f) {
        const int r0 = m0 + wm * 64 + f * 16 + grp;
        const int r1 = r0 + 8;
        const float s0 = __ldg(g_s + r0);
        const float s1 = __ldg(g_s + r1);
        const float* xr0 = x + (size_t)r0 * DDIM;
        const float* xr1 = x + (size_t)r1 * DDIM;
        float* yr0 = y + (size_t)r0 * DDIM;
        float* yr1 = y + (size_t)r1 * DDIM;
#pragma unroll
        for (int g = 0; g < 8; ++g) {
            const int c = n0 + wn * 64 + g * 8 + 2 * qid;
            const float2 bv = *(const float2*)(b1 + c);
            const float2 x0 = *(const float2*)(xr0 + c);
            const float2 x1 = *(const float2*)(xr1 + c);
            float2 o0, o1;
            o0.x = x0.x * softplus_f(acc[f][g][0] + bv.x) * s0;
            o0.y = x0.y * softplus_f(acc[f][g][1] + bv.y) * s0;
            o1.x = x1.x * softplus_f(acc[f][g][2] + bv.x) * s1;
            o1.y = x1.y * softplus_f(acc[f][g][3] + bv.y) * s1;
            *(float2*)(yr0 + c) = o0;
            *(float2*)(yr1 + c) = o1;
        }
    }
}

// ---------------------------------------------------------------------------
// Launch
// ---------------------------------------------------------------------------
extern "C" void kernel_launch(void* const* d_in, const int* in_sizes, int n_in,
                              void* d_out, int out_size) {
    const float* x  = (const float*)d_in[0];
    const float* W1 = (const float*)d_in[1];
    const float* b1 = (const float*)d_in[2];
    const float* W2 = (const float*)d_in[3];
    const float* b2 = (const float*)d_in[4];
    const float* W3 = (const float*)d_in[5];
    const float* b3 = (const float*)d_in[6];
    float* y = (float*)d_out;

    s6_pack_w23<<<32, 256>>>(W2, W3);
    s6_prep<<<PREP_BLOCKS + COPY_BLOCKS, 256>>>(x, W1, b2, b3);

    cudaFuncSetAttribute(s6_gemm, cudaFuncAttributeMaxDynamicSharedMemorySize, G_SMEM_BYTES);
    s6_gemm<<<dim3(DDIM / BN, NTOK / BM), GTHREADS, G_SMEM_BYTES>>>(x, b1, y);
}